// round 1
// baseline (speedup 1.0000x reference)
#include <cuda_runtime.h>
#include <math.h>

#define T_LEN 256
#define BATCH 64
#define INDIM 512
#define HDIM  1024
#define M_TOT (T_LEN * BATCH)   /* 16384 */
#define G4    (4 * HDIM)        /* 4096  */
#define NBLK_LSTM 128

/* ------------------------------------------------------------------ */
/* Scratch (static device allocations — the sanctioned workaround)     */
/* ------------------------------------------------------------------ */
__device__ float    g_xproj [M_TOT * G4];     /* 268 MB */
__device__ float    g_hs    [M_TOT * HDIM];   /* 67 MB  */
__device__ float    g_logits[M_TOT * INDIM];  /* 33 MB  */
__device__ unsigned g_bar   [T_LEN];          /* ticket barrier slots */

/* ------------------------------------------------------------------ */
/* Packed fp32x2 helpers (Blackwell FFMA2 — 2x fp32 throughput)        */
/* ------------------------------------------------------------------ */
__device__ __forceinline__ void fma2(unsigned long long &d,
                                     unsigned long long a,
                                     unsigned long long b) {
    asm("fma.rn.f32x2 %0, %1, %2, %0;" : "+l"(d) : "l"(a), "l"(b));
}
__device__ __forceinline__ unsigned long long dup2(float a) {
    unsigned long long r;
    asm("mov.b64 %0, {%1, %1};" : "=l"(r) : "f"(a));
    return r;
}
__device__ __forceinline__ float2 unpk(unsigned long long v) {
    float2 r;
    asm("mov.b64 {%0, %1}, %2;" : "=f"(r.x), "=f"(r.y) : "l"(v));
    return r;
}
__device__ __forceinline__ float sigmoidf_(float x) {
    return 1.0f / (1.0f + expf(-x));
}

/* ------------------------------------------------------------------ */
/* GEMM:  C[m][n] = sum_k A[m][k] * B[n][k] + bias[n]  (NT, fp32)     */
/* MODE 0: A = Aext (inp),  C = g_xproj, add img on rows m < 64       */
/* MODE 1: A = g_hs,        C = g_logits                              */
/* Tile 128x128x16, 256 threads, 8x8 micro-tile, f32x2 accumulators.  */
/* ------------------------------------------------------------------ */
template <int KDIM, int NDIM, int MODE>
__global__ __launch_bounds__(256, 2)
void gemm_nt(const float* __restrict__ Aext,
             const float* __restrict__ B,
             const float* __restrict__ bias,
             const float* __restrict__ img) {
    __shared__ __align__(16) float As[16][132];
    __shared__ __align__(16) float Bs[16][132];

    const float* __restrict__ Ap = (MODE == 0) ? Aext : g_hs;
    float* __restrict__       Cp = (MODE == 0) ? g_xproj : g_logits;

    const int bm  = blockIdx.y * 128;
    const int bn  = blockIdx.x * 128;
    const int tid = threadIdx.x;
    const int tx  = tid & 15;   /* n-tile coord */
    const int ty  = tid >> 4;   /* m-tile coord */

    unsigned long long acc[8][4];
#pragma unroll
    for (int i = 0; i < 8; i++)
#pragma unroll
        for (int j = 0; j < 4; j++) acc[i][j] = 0ull;

    const int lrow = tid >> 2;  /* 0..63 */
    const int lcol = tid & 3;   /* float4 slot within 16-wide k */

    for (int kt = 0; kt < KDIM; kt += 16) {
#pragma unroll
        for (int p = 0; p < 2; p++) {
            const int row = lrow + p * 64;
            float4 a4 = *(const float4*)(Ap + (size_t)(bm + row) * KDIM + kt + lcol * 4);
            float4 b4 = *(const float4*)(B  + (size_t)(bn + row) * KDIM + kt + lcol * 4);
            As[lcol * 4 + 0][row] = a4.x; As[lcol * 4 + 1][row] = a4.y;
            As[lcol * 4 + 2][row] = a4.z; As[lcol * 4 + 3][row] = a4.w;
            Bs[lcol * 4 + 0][row] = b4.x; Bs[lcol * 4 + 1][row] = b4.y;
            Bs[lcol * 4 + 2][row] = b4.z; Bs[lcol * 4 + 3][row] = b4.w;
        }
        __syncthreads();
#pragma unroll
        for (int kk = 0; kk < 16; kk++) {
            float4 a0 = *(const float4*)&As[kk][ty * 8];
            float4 a1 = *(const float4*)&As[kk][ty * 8 + 4];
            ulonglong2 b0 = *(const ulonglong2*)&Bs[kk][tx * 4];
            ulonglong2 b1 = *(const ulonglong2*)&Bs[kk][64 + tx * 4];
            unsigned long long ad[8];
            ad[0] = dup2(a0.x); ad[1] = dup2(a0.y); ad[2] = dup2(a0.z); ad[3] = dup2(a0.w);
            ad[4] = dup2(a1.x); ad[5] = dup2(a1.y); ad[6] = dup2(a1.z); ad[7] = dup2(a1.w);
#pragma unroll
            for (int i = 0; i < 8; i++) {
                fma2(acc[i][0], ad[i], b0.x);
                fma2(acc[i][1], ad[i], b0.y);
                fma2(acc[i][2], ad[i], b1.x);
                fma2(acc[i][3], ad[i], b1.y);
            }
        }
        __syncthreads();
    }

    /* epilogue */
    float4 bs0 = *(const float4*)&bias[bn + tx * 4];
    float4 bs1 = *(const float4*)&bias[bn + 64 + tx * 4];
#pragma unroll
    for (int i = 0; i < 8; i++) {
        const int m = bm + ty * 8 + i;
        float2 p01 = unpk(acc[i][0]);
        float2 p23 = unpk(acc[i][1]);
        float2 q01 = unpk(acc[i][2]);
        float2 q23 = unpk(acc[i][3]);
        float4 o0 = make_float4(p01.x + bs0.x, p01.y + bs0.y, p23.x + bs0.z, p23.y + bs0.w);
        float4 o1 = make_float4(q01.x + bs1.x, q01.y + bs1.y, q23.x + bs1.z, q23.y + bs1.w);
        if (MODE == 0 && m < BATCH) {
            /* t == 0 row: add img tiled 4x along features (n mod 1024) */
            const int n0 = bn + tx * 4;
            const int n1 = bn + 64 + tx * 4;
            o0.x += img[m * HDIM + ((n0 + 0) & (HDIM - 1))];
            o0.y += img[m * HDIM + ((n0 + 1) & (HDIM - 1))];
            o0.z += img[m * HDIM + ((n0 + 2) & (HDIM - 1))];
            o0.w += img[m * HDIM + ((n0 + 3) & (HDIM - 1))];
            o1.x += img[m * HDIM + ((n1 + 0) & (HDIM - 1))];
            o1.y += img[m * HDIM + ((n1 + 1) & (HDIM - 1))];
            o1.z += img[m * HDIM + ((n1 + 2) & (HDIM - 1))];
            o1.w += img[m * HDIM + ((n1 + 3) & (HDIM - 1))];
        }
        *(float4*)(Cp + (size_t)m * NDIM + bn + tx * 4)      = o0;
        *(float4*)(Cp + (size_t)m * NDIM + bn + 64 + tx * 4) = o1;
    }
}

/* ------------------------------------------------------------------ */
/* Replay-safe ticket grid barrier (all 128 CTAs co-resident: 1/SM).  */
/* Ticket blocks per launch are contiguous, so target = next multiple */
/* of NBLK above own ticket. Counters never reset.                    */
/* ------------------------------------------------------------------ */
__device__ __forceinline__ void grid_barrier(int slot) {
    __syncthreads();
    if (threadIdx.x == 0) {
        __threadfence();
        unsigned ticket = atomicAdd(&g_bar[slot], 1u);
        unsigned target = (ticket / NBLK_LSTM + 1u) * NBLK_LSTM;
        while (*((volatile unsigned*)&g_bar[slot]) < target) { }
        __threadfence();
    }
    __syncthreads();
}

/* ------------------------------------------------------------------ */
/* Persistent LSTM recurrence.                                        */
/* 128 CTAs x 256 threads. CTA owns 8 hidden units -> 32 Whh rows in  */
/* SMEM (128 KB). Thread = (2 batches, 1 unit, all 4 gates); c kept   */
/* in registers. h broadcast via global hs + per-step grid barrier.   */
/* ------------------------------------------------------------------ */
#define KC 256  /* h k-chunk staged in smem: 64*KC floats = 64 KB */

__global__ __launch_bounds__(256, 1)
void lstm_kernel(const float* __restrict__ Whh,
                 const float* __restrict__ bhh) {
    extern __shared__ __align__(16) float smem[];
    float* Ws = smem;                 /* [32][1024] : row r = u*4+g */
    float* hh = smem + 32 * HDIM;     /* [64][KC]                   */

    const int tid = threadIdx.x;
    const int j0  = blockIdx.x * 8;
    const int u   = tid & 7;
    const int bg  = tid >> 3;
    const int b0  = bg * 2;
    const int b1  = b0 + 1;
    const int jj  = j0 + u;

    /* stage this CTA's 32 Whh rows into SMEM (once) */
    for (int idx = tid; idx < 32 * 256; idx += 256) {
        const int r  = idx >> 8;        /* 0..31 */
        const int k4 = idx & 255;       /* float4 index in row */
        const int uu = r >> 2, gg = r & 3;
        float4 w = *(const float4*)&Whh[(size_t)(gg * HDIM + j0 + uu) * HDIM + k4 * 4];
        *(float4*)&Ws[r * HDIM + k4 * 4] = w;
    }
    float bh[4];
#pragma unroll
    for (int g = 0; g < 4; g++) bh[g] = bhh[g * HDIM + jj];
    float c0 = 0.0f, c1 = 0.0f;
    __syncthreads();

    const float* w0p = Ws + (u * 4 + 0) * HDIM;
    const float* w1p = Ws + (u * 4 + 1) * HDIM;
    const float* w2p = Ws + (u * 4 + 2) * HDIM;
    const float* w3p = Ws + (u * 4 + 3) * HDIM;

    for (int t = 0; t < T_LEN; t++) {
        float pre0[4], pre1[4];
#pragma unroll
        for (int g = 0; g < 4; g++) {
            pre0[g] = g_xproj[(size_t)(t * BATCH + b0) * G4 + g * HDIM + jj] + bh[g];
            pre1[g] = g_xproj[(size_t)(t * BATCH + b1) * G4 + g * HDIM + jj] + bh[g];
        }

        if (t > 0) {
            unsigned long long aA0[4] = {0,0,0,0}, aB0[4] = {0,0,0,0};
            unsigned long long aA1[4] = {0,0,0,0}, aB1[4] = {0,0,0,0};
            const float* __restrict__ hprev = g_hs + (size_t)(t - 1) * BATCH * HDIM;
            for (int ch = 0; ch < 4; ch++) {
                /* stage h chunk [64][KC] */
                for (int idx = tid; idx < 64 * (KC / 4); idx += 256) {
                    const int bb = idx >> 6;
                    const int k4 = idx & 63;
                    *(float4*)&hh[bb * KC + k4 * 4] =
                        *(const float4*)&hprev[bb * HDIM + ch * KC + k4 * 4];
                }
                __syncthreads();
                const float* h0b = hh + b0 * KC;
                const float* h1b = hh + b1 * KC;
                const int co = ch * KC;
#pragma unroll 8
                for (int k = 0; k < KC; k += 4) {
                    ulonglong2 H0 = *(const ulonglong2*)(h0b + k);
                    ulonglong2 H1 = *(const ulonglong2*)(h1b + k);
                    ulonglong2 W0 = *(const ulonglong2*)(w0p + co + k);
                    ulonglong2 W1 = *(const ulonglong2*)(w1p + co + k);
                    ulonglong2 W2 = *(const ulonglong2*)(w2p + co + k);
                    ulonglong2 W3 = *(const ulonglong2*)(w3p + co + k);
                    fma2(aA0[0], H0.x, W0.x); fma2(aB0[0], H0.y, W0.y);
                    fma2(aA0[1], H0.x, W1.x); fma2(aB0[1], H0.y, W1.y);
                    fma2(aA0[2], H0.x, W2.x); fma2(aB0[2], H0.y, W2.y);
                    fma2(aA0[3], H0.x, W3.x); fma2(aB0[3], H0.y, W3.y);
                    fma2(aA1[0], H1.x, W0.x); fma2(aB1[0], H1.y, W0.y);
                    fma2(aA1[1], H1.x, W1.x); fma2(aB1[1], H1.y, W1.y);
                    fma2(aA1[2], H1.x, W2.x); fma2(aB1[2], H1.y, W2.y);
                    fma2(aA1[3], H1.x, W3.x); fma2(aB1[3], H1.y, W3.y);
                }
                __syncthreads();
            }
#pragma unroll
            for (int g = 0; g < 4; g++) {
                float2 x = unpk(aA0[g]); float2 y = unpk(aB0[g]);
                pre0[g] += (x.x + x.y) + (y.x + y.y);
                float2 z = unpk(aA1[g]); float2 w = unpk(aB1[g]);
                pre1[g] += (z.x + z.y) + (w.x + w.y);
            }
        }

        /* gate math: i,f,g,o */
        {
            float ig = sigmoidf_(pre0[0]);
            float fg = sigmoidf_(pre0[1]);
            float gg = tanhf(pre0[2]);
            float og = sigmoidf_(pre0[3]);
            c0 = fg * c0 + ig * gg;
            g_hs[(size_t)t * BATCH * HDIM + b0 * HDIM + jj] = og * tanhf(c0);
        }
        {
            float ig = sigmoidf_(pre1[0]);
            float fg = sigmoidf_(pre1[1]);
            float gg = tanhf(pre1[2]);
            float og = sigmoidf_(pre1[3]);
            c1 = fg * c1 + ig * gg;
            g_hs[(size_t)t * BATCH * HDIM + b1 * HDIM + jj] = og * tanhf(c1);
        }

        if (t < T_LEN - 1) grid_barrier(t);
    }
}

/* ------------------------------------------------------------------ */
/* Row-wise log_softmax over 512 logits -> d_out                      */
/* ------------------------------------------------------------------ */
__global__ __launch_bounds__(256)
void logsoftmax_kernel(float* __restrict__ out) {
    __shared__ float red[8];
    const int row = blockIdx.x;
    const int tid = threadIdx.x;
    const float* x = g_logits + (size_t)row * INDIM;
    float v0 = x[tid];
    float v1 = x[tid + 256];

    float m = fmaxf(v0, v1);
#pragma unroll
    for (int o = 16; o; o >>= 1) m = fmaxf(m, __shfl_xor_sync(0xffffffffu, m, o));
    if ((tid & 31) == 0) red[tid >> 5] = m;
    __syncthreads();
    float M = fmaxf(fmaxf(fmaxf(red[0], red[1]), fmaxf(red[2], red[3])),
                    fmaxf(fmaxf(red[4], red[5]), fmaxf(red[6], red[7])));
    __syncthreads();

    float s = expf(v0 - M) + expf(v1 - M);
#pragma unroll
    for (int o = 16; o; o >>= 1) s += __shfl_xor_sync(0xffffffffu, s, o);
    if ((tid & 31) == 0) red[tid >> 5] = s;
    __syncthreads();
    float S = (red[0] + red[1]) + (red[2] + red[3]) +
              (red[4] + red[5]) + (red[6] + red[7]);
    float lse = M + logf(S);

    out[(size_t)row * INDIM + tid]       = v0 - lse;
    out[(size_t)row * INDIM + tid + 256] = v1 - lse;
}

/* ------------------------------------------------------------------ */
extern "C" void kernel_launch(void* const* d_in, const int* in_sizes, int n_in,
                              void* d_out, int out_size) {
    const float* inp  = (const float*)d_in[0];
    const float* img  = (const float*)d_in[1];
    const float* Wxh  = (const float*)d_in[2];
    const float* bxh  = (const float*)d_in[3];
    const float* Whh  = (const float*)d_in[4];
    const float* bhh  = (const float*)d_in[5];
    const float* Wout = (const float*)d_in[6];
    const float* bout = (const float*)d_in[7];
    float* out = (float*)d_out;

    const int lstm_smem = (32 * HDIM + 64 * KC) * (int)sizeof(float); /* 192 KB */
    cudaFuncSetAttribute(lstm_kernel,
                         cudaFuncAttributeMaxDynamicSharedMemorySize, lstm_smem);

    /* 1) xproj = inp @ Wxh^T + bxh (+ img4 on t=0 rows) */
    gemm_nt<INDIM, G4, 0><<<dim3(G4 / 128, M_TOT / 128), 256>>>(inp, Wxh, bxh, img);

    /* 2) persistent LSTM recurrence -> g_hs */
    lstm_kernel<<<NBLK_LSTM, 256, lstm_smem>>>(Whh, bhh);

    /* 3) logits = hs @ Wout^T + bout */
    gemm_nt<HDIM, INDIM, 1><<<dim3(INDIM / 128, M_TOT / 128), 256>>>(nullptr, Wout, bout, nullptr);

    /* 4) log_softmax -> d_out */
    logsoftmax_kernel<<<M_TOT, 256>>>(out);
}

// round 2
// speedup vs baseline: 4.2049x; 4.2049x over previous
#include <cuda_runtime.h>
#include <math.h>

#define T_LEN 256
#define BATCH 64
#define INDIM 512
#define HDIM  1024
#define M_TOT (T_LEN * BATCH)   /* 16384 */
#define G4    (4 * HDIM)        /* 4096  */
#define NBLK_LSTM 128

/* ------------------------------------------------------------------ */
/* Scratch (static device allocations — the sanctioned workaround)     */
/* ------------------------------------------------------------------ */
__device__ float    g_xproj [M_TOT * G4];     /* 268 MB */
__device__ float    g_hs    [M_TOT * HDIM];   /* 67 MB  */
__device__ float    g_logits[M_TOT * INDIM];  /* 33 MB  */
__device__ unsigned g_bar   [T_LEN];          /* ticket barrier slots */

/* ------------------------------------------------------------------ */
/* Packed fp32x2 helpers (Blackwell FFMA2 — 2x fp32 throughput)        */
/* ------------------------------------------------------------------ */
__device__ __forceinline__ void fma2(unsigned long long &d,
                                     unsigned long long a,
                                     unsigned long long b) {
    asm("fma.rn.f32x2 %0, %1, %2, %0;" : "+l"(d) : "l"(a), "l"(b));
}
__device__ __forceinline__ unsigned long long dup2(float a) {
    unsigned long long r;
    asm("mov.b64 %0, {%1, %1};" : "=l"(r) : "f"(a));
    return r;
}
__device__ __forceinline__ float2 unpk(unsigned long long v) {
    float2 r;
    asm("mov.b64 {%0, %1}, %2;" : "=f"(r.x), "=f"(r.y) : "l"(v));
    return r;
}
__device__ __forceinline__ float sigmoidf_(float x) {
    return 1.0f / (1.0f + expf(-x));
}

/* ------------------------------------------------------------------ */
/* GEMM:  C[m][n] = sum_k A[m][k] * B[n][k] + bias[n]  (NT, fp32)     */
/* (unchanged from Round 1 — isolating the LSTM fix this round)       */
/* ------------------------------------------------------------------ */
template <int KDIM, int NDIM, int MODE>
__global__ __launch_bounds__(256, 2)
void gemm_nt(const float* __restrict__ Aext,
             const float* __restrict__ B,
             const float* __restrict__ bias,
             const float* __restrict__ img) {
    __shared__ __align__(16) float As[16][132];
    __shared__ __align__(16) float Bs[16][132];

    const float* __restrict__ Ap = (MODE == 0) ? Aext : g_hs;
    float* __restrict__       Cp = (MODE == 0) ? g_xproj : g_logits;

    const int bm  = blockIdx.y * 128;
    const int bn  = blockIdx.x * 128;
    const int tid = threadIdx.x;
    const int tx  = tid & 15;
    const int ty  = tid >> 4;

    unsigned long long acc[8][4];
#pragma unroll
    for (int i = 0; i < 8; i++)
#pragma unroll
        for (int j = 0; j < 4; j++) acc[i][j] = 0ull;

    const int lrow = tid >> 2;
    const int lcol = tid & 3;

    for (int kt = 0; kt < KDIM; kt += 16) {
#pragma unroll
        for (int p = 0; p < 2; p++) {
            const int row = lrow + p * 64;
            float4 a4 = *(const float4*)(Ap + (size_t)(bm + row) * KDIM + kt + lcol * 4);
            float4 b4 = *(const float4*)(B  + (size_t)(bn + row) * KDIM + kt + lcol * 4);
            As[lcol * 4 + 0][row] = a4.x; As[lcol * 4 + 1][row] = a4.y;
            As[lcol * 4 + 2][row] = a4.z; As[lcol * 4 + 3][row] = a4.w;
            Bs[lcol * 4 + 0][row] = b4.x; Bs[lcol * 4 + 1][row] = b4.y;
            Bs[lcol * 4 + 2][row] = b4.z; Bs[lcol * 4 + 3][row] = b4.w;
        }
        __syncthreads();
#pragma unroll
        for (int kk = 0; kk < 16; kk++) {
            float4 a0 = *(const float4*)&As[kk][ty * 8];
            float4 a1 = *(const float4*)&As[kk][ty * 8 + 4];
            ulonglong2 b0 = *(const ulonglong2*)&Bs[kk][tx * 4];
            ulonglong2 b1 = *(const ulonglong2*)&Bs[kk][64 + tx * 4];
            unsigned long long ad[8];
            ad[0] = dup2(a0.x); ad[1] = dup2(a0.y); ad[2] = dup2(a0.z); ad[3] = dup2(a0.w);
            ad[4] = dup2(a1.x); ad[5] = dup2(a1.y); ad[6] = dup2(a1.z); ad[7] = dup2(a1.w);
#pragma unroll
            for (int i = 0; i < 8; i++) {
                fma2(acc[i][0], ad[i], b0.x);
                fma2(acc[i][1], ad[i], b0.y);
                fma2(acc[i][2], ad[i], b1.x);
                fma2(acc[i][3], ad[i], b1.y);
            }
        }
        __syncthreads();
    }

    float4 bs0 = *(const float4*)&bias[bn + tx * 4];
    float4 bs1 = *(const float4*)&bias[bn + 64 + tx * 4];
#pragma unroll
    for (int i = 0; i < 8; i++) {
        const int m = bm + ty * 8 + i;
        float2 p01 = unpk(acc[i][0]);
        float2 p23 = unpk(acc[i][1]);
        float2 q01 = unpk(acc[i][2]);
        float2 q23 = unpk(acc[i][3]);
        float4 o0 = make_float4(p01.x + bs0.x, p01.y + bs0.y, p23.x + bs0.z, p23.y + bs0.w);
        float4 o1 = make_float4(q01.x + bs1.x, q01.y + bs1.y, q23.x + bs1.z, q23.y + bs1.w);
        if (MODE == 0 && m < BATCH) {
            const int n0 = bn + tx * 4;
            const int n1 = bn + 64 + tx * 4;
            o0.x += img[m * HDIM + ((n0 + 0) & (HDIM - 1))];
            o0.y += img[m * HDIM + ((n0 + 1) & (HDIM - 1))];
            o0.z += img[m * HDIM + ((n0 + 2) & (HDIM - 1))];
            o0.w += img[m * HDIM + ((n0 + 3) & (HDIM - 1))];
            o1.x += img[m * HDIM + ((n1 + 0) & (HDIM - 1))];
            o1.y += img[m * HDIM + ((n1 + 1) & (HDIM - 1))];
            o1.z += img[m * HDIM + ((n1 + 2) & (HDIM - 1))];
            o1.w += img[m * HDIM + ((n1 + 3) & (HDIM - 1))];
        }
        *(float4*)(Cp + (size_t)m * NDIM + bn + tx * 4)      = o0;
        *(float4*)(Cp + (size_t)m * NDIM + bn + 64 + tx * 4) = o1;
    }
}

/* ------------------------------------------------------------------ */
/* Replay-safe ticket grid barrier (128 CTAs, all co-resident, 1/SM). */
/* ------------------------------------------------------------------ */
__device__ __forceinline__ void grid_barrier(int slot) {
    __syncthreads();
    if (threadIdx.x == 0) {
        __threadfence();
        unsigned ticket = atomicAdd(&g_bar[slot], 1u);
        unsigned target = (ticket / NBLK_LSTM + 1u) * NBLK_LSTM;
        while (*((volatile unsigned*)&g_bar[slot]) < target) { }
        __threadfence();
    }
    __syncthreads();
}

/* ------------------------------------------------------------------ */
/* Persistent LSTM recurrence — conflict-free rewrite.                */
/*                                                                    */
/* 128 CTAs x 256 thr. CTA owns 8 hidden units (32 gate rows).        */
/* Whh staged in k-blocked SMEM: Ws[kq][r=0..31][4 floats]            */
/*   -> W LDS.128: 32 lanes read contiguous 512B, conflict-free.      */
/* Thread = (r = u*4+g, batch-octet). H loads are warp-broadcast.     */
/* Each W.128 reused across 8 batches: 9 LDS.128 per 16 fma2.         */
/* Gate phase: pre[b][33] padded tile, bank-permutation reads.        */
/* ------------------------------------------------------------------ */
#define KC 256  /* h k-chunk staged in smem: 64*KC floats = 64 KB */

__global__ __launch_bounds__(256, 1)
void lstm_kernel(const float* __restrict__ Whh,
                 const float* __restrict__ bhh) {
    extern __shared__ __align__(16) float smem[];
    float* Ws  = smem;                       /* [256 kq][32 r][4] = 128 KB */
    float* hh  = smem + 32 * HDIM;           /* [64][KC]          =  64 KB */
    float* pre = hh + 64 * KC;               /* [64][33]          = 8.25 KB */

    const int tid = threadIdx.x;
    const int j0  = blockIdx.x * 8;

    /* accumulate identity: warp = 32 gate-rows, thread = (r, b-octet) */
    const int r  = tid & 31;           /* r = u*4 + g             */
    const int bo = tid >> 5;           /* batch octet 0..7        */
    const int u  = r >> 2;
    const int g  = r & 3;
    const int jj = j0 + u;

    /* gate identity: cells (gu, gb) and (gu, gb+32) */
    const int gu = tid & 7;
    const int gb = tid >> 3;           /* 0..31 */
    const int gjj = j0 + gu;

    /* stage Whh into k-blocked layout (once) */
    for (int idx = tid; idx < 32 * 256; idx += 256) {
        const int rr = idx & 31;
        const int kq = idx >> 5;           /* 0..255 */
        const int uu = rr >> 2, gg = rr & 3;
        float4 w = *(const float4*)&Whh[(size_t)(gg * HDIM + j0 + uu) * HDIM + kq * 4];
        *(float4*)&Ws[kq * 128 + rr * 4] = w;
    }
    const float bias = bhh[g * HDIM + jj];
    float c0 = 0.0f, c1 = 0.0f;
    __syncthreads();

    for (int t = 0; t < T_LEN; t++) {
        unsigned long long acc[8];
#pragma unroll
        for (int b = 0; b < 8; b++) acc[b] = 0ull;

        if (t > 0) {
            const float* __restrict__ hprev = g_hs + (size_t)(t - 1) * BATCH * HDIM;
#pragma unroll 1
            for (int ch = 0; ch < 4; ch++) {
                /* stage h chunk [64][KC] */
                for (int idx = tid; idx < 64 * (KC / 4); idx += 256) {
                    const int bb = idx >> 6;
                    const int k4 = idx & 63;
                    *(float4*)&hh[bb * KC + k4 * 4] =
                        *(const float4*)&hprev[bb * HDIM + ch * KC + k4 * 4];
                }
                __syncthreads();

                const float* wbase = Ws + (ch * 64) * 128 + r * 4;
                const float* hbase = hh + bo * 8 * KC;
#pragma unroll 4
                for (int kq = 0; kq < 64; kq++) {
                    ulonglong2 W = *(const ulonglong2*)(wbase + kq * 128);
#pragma unroll
                    for (int b = 0; b < 8; b++) {
                        ulonglong2 H = *(const ulonglong2*)(hbase + b * KC + kq * 4);
                        fma2(acc[b], H.x, W.x);
                        fma2(acc[b], H.y, W.y);
                    }
                }
                __syncthreads();
            }
        }

        /* pre-activations -> padded smem tile */
        {
            const float* xp = g_xproj + (size_t)t * BATCH * G4 + g * HDIM + jj;
#pragma unroll
            for (int b = 0; b < 8; b++) {
                float2 p = unpk(acc[b]);
                const int bb = bo * 8 + b;
                pre[bb * 33 + r] = p.x + p.y + bias + xp[(size_t)bb * G4];
            }
        }
        __syncthreads();

        /* gate math: 2 cells per thread, conflict-free pre reads */
        {
            const float* p0 = pre + gb * 33 + gu * 4;
            float ig = sigmoidf_(p0[0]);
            float fg = sigmoidf_(p0[1]);
            float gg = tanhf(p0[2]);
            float og = sigmoidf_(p0[3]);
            c0 = fg * c0 + ig * gg;
            g_hs[(size_t)t * BATCH * HDIM + (size_t)gb * HDIM + gjj] = og * tanhf(c0);
        }
        {
            const float* p1 = pre + (gb + 32) * 33 + gu * 4;
            float ig = sigmoidf_(p1[0]);
            float fg = sigmoidf_(p1[1]);
            float gg = tanhf(p1[2]);
            float og = sigmoidf_(p1[3]);
            c1 = fg * c1 + ig * gg;
            g_hs[(size_t)t * BATCH * HDIM + (size_t)(gb + 32) * HDIM + gjj] = og * tanhf(c1);
        }

        if (t < T_LEN - 1) grid_barrier(t);
    }
}

/* ------------------------------------------------------------------ */
/* Row-wise log_softmax over 512 logits -> d_out                      */
/* ------------------------------------------------------------------ */
__global__ __launch_bounds__(256)
void logsoftmax_kernel(float* __restrict__ out) {
    __shared__ float red[8];
    const int row = blockIdx.x;
    const int tid = threadIdx.x;
    const float* x = g_logits + (size_t)row * INDIM;
    float v0 = x[tid];
    float v1 = x[tid + 256];

    float m = fmaxf(v0, v1);
#pragma unroll
    for (int o = 16; o; o >>= 1) m = fmaxf(m, __shfl_xor_sync(0xffffffffu, m, o));
    if ((tid & 31) == 0) red[tid >> 5] = m;
    __syncthreads();
    float M = fmaxf(fmaxf(fmaxf(red[0], red[1]), fmaxf(red[2], red[3])),
                    fmaxf(fmaxf(red[4], red[5]), fmaxf(red[6], red[7])));
    __syncthreads();

    float s = expf(v0 - M) + expf(v1 - M);
#pragma unroll
    for (int o = 16; o; o >>= 1) s += __shfl_xor_sync(0xffffffffu, s, o);
    if ((tid & 31) == 0) red[tid >> 5] = s;
    __syncthreads();
    float S = (red[0] + red[1]) + (red[2] + red[3]) +
              (red[4] + red[5]) + (red[6] + red[7]);
    float lse = M + logf(S);

    out[(size_t)row * INDIM + tid]       = v0 - lse;
    out[(size_t)row * INDIM + tid + 256] = v1 - lse;
}

/* ------------------------------------------------------------------ */
extern "C" void kernel_launch(void* const* d_in, const int* in_sizes, int n_in,
                              void* d_out, int out_size) {
    const float* inp  = (const float*)d_in[0];
    const float* img  = (const float*)d_in[1];
    const float* Wxh  = (const float*)d_in[2];
    const float* bxh  = (const float*)d_in[3];
    const float* Whh  = (const float*)d_in[4];
    const float* bhh  = (const float*)d_in[5];
    const float* Wout = (const float*)d_in[6];
    const float* bout = (const float*)d_in[7];
    float* out = (float*)d_out;

    const int lstm_smem = (32 * HDIM + 64 * KC + 64 * 33) * (int)sizeof(float); /* ~200 KB */
    cudaFuncSetAttribute(lstm_kernel,
                         cudaFuncAttributeMaxDynamicSharedMemorySize, lstm_smem);

    /* 1) xproj = inp @ Wxh^T + bxh (+ img4 on t=0 rows) */
    gemm_nt<INDIM, G4, 0><<<dim3(G4 / 128, M_TOT / 128), 256>>>(inp, Wxh, bxh, img);

    /* 2) persistent LSTM recurrence -> g_hs */
    lstm_kernel<<<NBLK_LSTM, 256, lstm_smem>>>(Whh, bhh);

    /* 3) logits = hs @ Wout^T + bout */
    gemm_nt<HDIM, INDIM, 1><<<dim3(INDIM / 128, M_TOT / 128), 256>>>(nullptr, Wout, bout, nullptr);

    /* 4) log_softmax -> d_out */
    logsoftmax_kernel<<<M_TOT, 256>>>(out);
}

// round 4
// speedup vs baseline: 4.2960x; 1.0217x over previous
#include <cuda_runtime.h>
#include <math.h>

#define T_LEN 256
#define BATCH 64
#define INDIM 512
#define HDIM  1024
#define M_TOT (T_LEN * BATCH)   /* 16384 */
#define G4    (4 * HDIM)        /* 4096  */
#define NBLK_LSTM 128

/* ------------------------------------------------------------------ */
/* Scratch (static device allocations)                                 */
/* ------------------------------------------------------------------ */
__device__ float    g_xproj [M_TOT * G4];     /* 268 MB */
__device__ float    g_hs    [M_TOT * HDIM];   /* 67 MB  */
__device__ float    g_logits[M_TOT * INDIM];  /* 33 MB  */
__device__ unsigned g_bar   [T_LEN];          /* ticket barrier slots */

/* ------------------------------------------------------------------ */
/* Packed fp32x2 + cp.async helpers                                    */
/* ------------------------------------------------------------------ */
__device__ __forceinline__ void fma2(unsigned long long &d,
                                     unsigned long long a,
                                     unsigned long long b) {
    asm("fma.rn.f32x2 %0, %1, %2, %0;" : "+l"(d) : "l"(a), "l"(b));
}
__device__ __forceinline__ unsigned long long dup2(float a) {
    unsigned long long r;
    asm("mov.b64 %0, {%1, %1};" : "=l"(r) : "f"(a));
    return r;
}
__device__ __forceinline__ float2 unpk(unsigned long long v) {
    float2 r;
    asm("mov.b64 {%0, %1}, %2;" : "=f"(r.x), "=f"(r.y) : "l"(v));
    return r;
}
__device__ __forceinline__ float sigmoidf_(float x) {
    return 1.0f / (1.0f + expf(-x));
}
__device__ __forceinline__ void cp_async16(float* smem_dst, const float* gsrc) {
    unsigned sa = (unsigned)__cvta_generic_to_shared(smem_dst);
    asm volatile("cp.async.cg.shared.global [%0], [%1], 16;\n" :: "r"(sa), "l"(gsrc));
}
__device__ __forceinline__ void cp_commit() {
    asm volatile("cp.async.commit_group;\n" ::: "memory");
}
__device__ __forceinline__ void cp_wait0() {
    asm volatile("cp.async.wait_group 0;\n" ::: "memory");
}
__device__ __forceinline__ void cp_wait1() {
    asm volatile("cp.async.wait_group 1;\n" ::: "memory");
}

/* ------------------------------------------------------------------ */
/* GEMM:  C[m][n] = sum_k A[m][k] * B[n][k] + bias[n]  (NT, fp32)     */
/* Pipelined: LDG of next k-tile issued before compute of current.    */
/* ------------------------------------------------------------------ */
template <int KDIM, int NDIM, int MODE>
__global__ __launch_bounds__(256, 2)
void gemm_nt(const float* __restrict__ Aext,
             const float* __restrict__ B,
             const float* __restrict__ bias,
             const float* __restrict__ img) {
    __shared__ __align__(16) float As[16][132];
    __shared__ __align__(16) float Bs[16][132];

    const float* __restrict__ Ap = (MODE == 0) ? Aext : g_hs;
    float* __restrict__       Cp = (MODE == 0) ? g_xproj : g_logits;

    const int bm  = blockIdx.y * 128;
    const int bn  = blockIdx.x * 128;
    const int tid = threadIdx.x;
    const int tx  = tid & 15;
    const int ty  = tid >> 4;

    unsigned long long acc[8][4];
#pragma unroll
    for (int i = 0; i < 8; i++)
#pragma unroll
        for (int j = 0; j < 4; j++) acc[i][j] = 0ull;

    const int lrow = tid >> 2;
    const int lcol = tid & 3;

    /* prefetch k-tile 0 into registers */
    float4 ra[2], rb[2];
#pragma unroll
    for (int p = 0; p < 2; p++) {
        const int row = lrow + p * 64;
        ra[p] = *(const float4*)(Ap + (size_t)(bm + row) * KDIM + lcol * 4);
        rb[p] = *(const float4*)(B  + (size_t)(bn + row) * KDIM + lcol * 4);
    }

    for (int kt = 0; kt < KDIM; kt += 16) {
        /* store current tile (transposed) to smem */
#pragma unroll
        for (int p = 0; p < 2; p++) {
            const int row = lrow + p * 64;
            As[lcol * 4 + 0][row] = ra[p].x; As[lcol * 4 + 1][row] = ra[p].y;
            As[lcol * 4 + 2][row] = ra[p].z; As[lcol * 4 + 3][row] = ra[p].w;
            Bs[lcol * 4 + 0][row] = rb[p].x; Bs[lcol * 4 + 1][row] = rb[p].y;
            Bs[lcol * 4 + 2][row] = rb[p].z; Bs[lcol * 4 + 3][row] = rb[p].w;
        }
        __syncthreads();

        /* issue LDG of the NEXT tile; latency hides under compute below */
        if (kt + 16 < KDIM) {
#pragma unroll
            for (int p = 0; p < 2; p++) {
                const int row = lrow + p * 64;
                ra[p] = *(const float4*)(Ap + (size_t)(bm + row) * KDIM + kt + 16 + lcol * 4);
                rb[p] = *(const float4*)(B  + (size_t)(bn + row) * KDIM + kt + 16 + lcol * 4);
            }
        }

#pragma unroll
        for (int kk = 0; kk < 16; kk++) {
            float4 a0 = *(const float4*)&As[kk][ty * 8];
            float4 a1 = *(const float4*)&As[kk][ty * 8 + 4];
            ulonglong2 b0 = *(const ulonglong2*)&Bs[kk][tx * 4];
            ulonglong2 b1 = *(const ulonglong2*)&Bs[kk][64 + tx * 4];
            unsigned long long ad[8];
            ad[0] = dup2(a0.x); ad[1] = dup2(a0.y); ad[2] = dup2(a0.z); ad[3] = dup2(a0.w);
            ad[4] = dup2(a1.x); ad[5] = dup2(a1.y); ad[6] = dup2(a1.z); ad[7] = dup2(a1.w);
#pragma unroll
            for (int i = 0; i < 8; i++) {
                fma2(acc[i][0], ad[i], b0.x);
                fma2(acc[i][1], ad[i], b0.y);
                fma2(acc[i][2], ad[i], b1.x);
                fma2(acc[i][3], ad[i], b1.y);
            }
        }
        __syncthreads();
    }

    float4 bs0 = *(const float4*)&bias[bn + tx * 4];
    float4 bs1 = *(const float4*)&bias[bn + 64 + tx * 4];
#pragma unroll
    for (int i = 0; i < 8; i++) {
        const int m = bm + ty * 8 + i;
        float2 p01 = unpk(acc[i][0]);
        float2 p23 = unpk(acc[i][1]);
        float2 q01 = unpk(acc[i][2]);
        float2 q23 = unpk(acc[i][3]);
        float4 o0 = make_float4(p01.x + bs0.x, p01.y + bs0.y, p23.x + bs0.z, p23.y + bs0.w);
        float4 o1 = make_float4(q01.x + bs1.x, q01.y + bs1.y, q23.x + bs1.z, q23.y + bs1.w);
        if (MODE == 0 && m < BATCH) {
            const int n0 = bn + tx * 4;
            const int n1 = bn + 64 + tx * 4;
            o0.x += img[m * HDIM + ((n0 + 0) & (HDIM - 1))];
            o0.y += img[m * HDIM + ((n0 + 1) & (HDIM - 1))];
            o0.z += img[m * HDIM + ((n0 + 2) & (HDIM - 1))];
            o0.w += img[m * HDIM + ((n0 + 3) & (HDIM - 1))];
            o1.x += img[m * HDIM + ((n1 + 0) & (HDIM - 1))];
            o1.y += img[m * HDIM + ((n1 + 1) & (HDIM - 1))];
            o1.z += img[m * HDIM + ((n1 + 2) & (HDIM - 1))];
            o1.w += img[m * HDIM + ((n1 + 3) & (HDIM - 1))];
        }
        *(float4*)(Cp + (size_t)m * NDIM + bn + tx * 4)      = o0;
        *(float4*)(Cp + (size_t)m * NDIM + bn + 64 + tx * 4) = o1;
    }
}

/* ------------------------------------------------------------------ */
/* Replay-safe ticket grid barrier (128 CTAs, all co-resident, 1/SM). */
/* ------------------------------------------------------------------ */
__device__ __forceinline__ void grid_barrier(int slot) {
    __syncthreads();
    if (threadIdx.x == 0) {
        __threadfence();
        unsigned ticket = atomicAdd(&g_bar[slot], 1u);
        unsigned target = (ticket / NBLK_LSTM + 1u) * NBLK_LSTM;
        while (*((volatile unsigned*)&g_bar[slot]) < target) { }
        __threadfence();
    }
    __syncthreads();
}

/* ------------------------------------------------------------------ */
/* Persistent LSTM recurrence — 512 thr, cp.async double-buffered h.  */
/* Warp = 32 gate-rows r; thread = (r, batch-quad q). acc packs k.    */
/* ------------------------------------------------------------------ */
#define KC2 128   /* h k-chunk: 64 x 128 floats = 32 KB, x2 buffers */

__global__ __launch_bounds__(512, 1)
void lstm_kernel(const float* __restrict__ Whh,
                 const float* __restrict__ bhh) {
    extern __shared__ __align__(16) float smem[];
    float* Ws  = smem;                       /* [256 kq][32 r][4] = 128 KB */
    float* hh  = smem + 32 * HDIM;           /* [2][64][KC2]      =  64 KB */
    float* pre = hh + 2 * 64 * KC2;          /* [64][33]          = 8.25 KB */

    const int tid = threadIdx.x;
    const int j0  = blockIdx.x * 8;

    /* accumulate identity */
    const int r  = tid & 31;           /* r = u*4 + g     */
    const int q  = tid >> 5;           /* batch quad 0..15 (== warp id) */
    const int u  = r >> 2;
    const int g  = r & 3;
    const int jj = j0 + u;

    /* gate identity: one cell per thread */
    const int gu  = tid & 7;
    const int gb  = tid >> 3;          /* 0..63 */
    const int gjj = j0 + gu;

    /* stage Whh into k-blocked layout (once) */
    for (int idx = tid; idx < 32 * 256; idx += 512) {
        const int rr = idx & 31;
        const int kq = idx >> 5;
        const int uu = rr >> 2, gg = rr & 3;
        float4 w = *(const float4*)&Whh[(size_t)(gg * HDIM + j0 + uu) * HDIM + kq * 4];
        *(float4*)&Ws[kq * 128 + rr * 4] = w;
    }
    const float bias = bhh[g * HDIM + jj];
    float c = 0.0f;
    __syncthreads();

    for (int t = 0; t < T_LEN; t++) {
        /* prefetch xproj for this thread's 4 batches (DRAM latency hidden
           under the whole h dot-product below) */
        float xp[4];
        {
            const float* xbase = g_xproj + (size_t)t * BATCH * G4 + g * HDIM + jj;
#pragma unroll
            for (int j = 0; j < 4; j++)
                xp[j] = __ldg(xbase + (size_t)(q * 4 + j) * G4);
        }

        unsigned long long acc[4] = {0ull, 0ull, 0ull, 0ull};

        if (t > 0) {
            const float* __restrict__ hprev = g_hs + (size_t)(t - 1) * BATCH * HDIM;

            /* prologue: stage chunk 0 -> buf 0 */
#pragma unroll
            for (int i = 0; i < 4; i++) {
                const int idx = tid + i * 512;
                const int bb = idx >> 5, k4 = idx & 31;
                cp_async16(&hh[bb * KC2 + k4 * 4], &hprev[bb * HDIM + k4 * 4]);
            }
            cp_commit();

#pragma unroll 1
            for (int ch = 0; ch < 8; ch++) {
                const int buf = ch & 1;
                if (ch < 7) {
                    float* dst = hh + ((ch + 1) & 1) * 64 * KC2;
#pragma unroll
                    for (int i = 0; i < 4; i++) {
                        const int idx = tid + i * 512;
                        const int bb = idx >> 5, k4 = idx & 31;
                        cp_async16(&dst[bb * KC2 + k4 * 4],
                                   &hprev[bb * HDIM + (ch + 1) * KC2 + k4 * 4]);
                    }
                    cp_commit();
                    cp_wait1();
                } else {
                    cp_wait0();
                }
                __syncthreads();

                const float* wbase = Ws + (ch * 32) * 128 + r * 4;
                const float* hbase = hh + buf * 64 * KC2 + (q * 4) * KC2;
#pragma unroll 8
                for (int kq = 0; kq < 32; kq++) {
                    ulonglong2 W = *(const ulonglong2*)(wbase + kq * 128);
#pragma unroll
                    for (int j = 0; j < 4; j++) {
                        ulonglong2 H = *(const ulonglong2*)(hbase + j * KC2 + kq * 4);
                        fma2(acc[j], H.x, W.x);
                        fma2(acc[j], H.y, W.y);
                    }
                }
                __syncthreads();
            }
        }

        /* pre-activations -> padded smem tile (conflict-free: +r per lane) */
#pragma unroll
        for (int j = 0; j < 4; j++) {
            float2 p = unpk(acc[j]);
            pre[(q * 4 + j) * 33 + r] = p.x + p.y + bias + xp[j];
        }
        __syncthreads();

        /* gate math: one (batch, unit) cell per thread */
        {
            const float* pg = pre + gb * 33 + gu * 4;
            float ig = sigmoidf_(pg[0]);
            float fg = sigmoidf_(pg[1]);
            float gg = tanhf(pg[2]);
            float og = sigmoidf_(pg[3]);
            c = fg * c + ig * gg;
            g_hs[(size_t)t * BATCH * HDIM + (size_t)gb * HDIM + gjj] = og * tanhf(c);
        }

        if (t < T_LEN - 1) grid_barrier(t);
    }
}

/* ------------------------------------------------------------------ */
/* Row-wise log_softmax over 512 logits -> d_out                      */
/* ------------------------------------------------------------------ */
__global__ __launch_bounds__(256)
void logsoftmax_kernel(float* __restrict__ out) {
    __shared__ float red[8];
    const int row = blockIdx.x;
    const int tid = threadIdx.x;
    const float* x = g_logits + (size_t)row * INDIM;
    float v0 = x[tid];
    float v1 = x[tid + 256];

    float m = fmaxf(v0, v1);
#pragma unroll
    for (int o = 16; o; o >>= 1) m = fmaxf(m, __shfl_xor_sync(0xffffffffu, m, o));
    if ((tid & 31) == 0) red[tid >> 5] = m;
    __syncthreads();
    float M = fmaxf(fmaxf(fmaxf(red[0], red[1]), fmaxf(red[2], red[3])),
                    fmaxf(fmaxf(red[4], red[5]), fmaxf(red[6], red[7])));
    __syncthreads();

    float s = expf(v0 - M) + expf(v1 - M);
#pragma unroll
    for (int o = 16; o; o >>= 1) s += __shfl_xor_sync(0xffffffffu, s, o);
    if ((tid & 31) == 0) red[tid >> 5] = s;
    __syncthreads();
    float S = (red[0] + red[1]) + (red[2] + red[3]) +
              (red[4] + red[5]) + (red[6] + red[7]);
    float lse = M + logf(S);

    out[(size_t)row * INDIM + tid]       = v0 - lse;
    out[(size_t)row * INDIM + tid + 256] = v1 - lse;
}

/* ------------------------------------------------------------------ */
extern "C" void kernel_launch(void* const* d_in, const int* in_sizes, int n_in,
                              void* d_out, int out_size) {
    const float* inp  = (const float*)d_in[0];
    const float* img  = (const float*)d_in[1];
    const float* Wxh  = (const float*)d_in[2];
    const float* bxh  = (const float*)d_in[3];
    const float* Whh  = (const float*)d_in[4];
    const float* bhh  = (const float*)d_in[5];
    const float* Wout = (const float*)d_in[6];
    const float* bout = (const float*)d_in[7];
    float* out = (float*)d_out;

    const int lstm_smem = (32 * HDIM + 2 * 64 * KC2 + 64 * 33) * (int)sizeof(float); /* ~200 KB */
    cudaFuncSetAttribute(lstm_kernel,
                         cudaFuncAttributeMaxDynamicSharedMemorySize, lstm_smem);

    /* 1) xproj = inp @ Wxh^T + bxh (+ img4 on t=0 rows) */
    gemm_nt<INDIM, G4, 0><<<dim3(G4 / 128, M_TOT / 128), 256>>>(inp, Wxh, bxh, img);

    /* 2) persistent LSTM recurrence -> g_hs */
    lstm_kernel<<<NBLK_LSTM, 512, lstm_smem>>>(Whh, bhh);

    /* 3) logits = hs @ Wout^T + bout */
    gemm_nt<HDIM, INDIM, 1><<<dim3(INDIM / 128, M_TOT / 128), 256>>>(nullptr, Wout, bout, nullptr);

    /* 4) log_softmax -> d_out */
    logsoftmax_kernel<<<M_TOT, 256>>>(out);
}

// round 5
// speedup vs baseline: 4.3626x; 1.0155x over previous
#include <cuda_runtime.h>
#include <math.h>

#define T_LEN 256
#define BATCH 64
#define INDIM 512
#define HDIM  1024
#define M_TOT (T_LEN * BATCH)   /* 16384 */
#define G4    (4 * HDIM)        /* 4096  */
#define NBLK_LSTM 128

/* ------------------------------------------------------------------ */
__device__ float    g_xproj [M_TOT * G4];
__device__ float    g_hs    [M_TOT * HDIM];
__device__ float    g_logits[M_TOT * INDIM];
__device__ unsigned g_bar   [T_LEN];

/* ------------------------------------------------------------------ */
__device__ __forceinline__ void fma2(unsigned long long &d,
                                     unsigned long long a,
                                     unsigned long long b) {
    asm("fma.rn.f32x2 %0, %1, %2, %0;" : "+l"(d) : "l"(a), "l"(b));
}
__device__ __forceinline__ unsigned long long dup2(float a) {
    unsigned long long r;
    asm("mov.b64 %0, {%1, %1};" : "=l"(r) : "f"(a));
    return r;
}
__device__ __forceinline__ float2 unpk(unsigned long long v) {
    float2 r;
    asm("mov.b64 {%0, %1}, %2;" : "=f"(r.x), "=f"(r.y) : "l"(v));
    return r;
}
__device__ __forceinline__ float sigmoidf_(float x) {
    return 1.0f / (1.0f + expf(-x));
}

/* ------------------------------------------------------------------ */
/* GEMM (unchanged from Round 3/4)                                    */
/* ------------------------------------------------------------------ */
template <int KDIM, int NDIM, int MODE>
__global__ __launch_bounds__(256, 2)
void gemm_nt(const float* __restrict__ Aext,
             const float* __restrict__ B,
             const float* __restrict__ bias,
             const float* __restrict__ img) {
    __shared__ __align__(16) float As[16][132];
    __shared__ __align__(16) float Bs[16][132];

    const float* __restrict__ Ap = (MODE == 0) ? Aext : g_hs;
    float* __restrict__       Cp = (MODE == 0) ? g_xproj : g_logits;

    const int bm  = blockIdx.y * 128;
    const int bn  = blockIdx.x * 128;
    const int tid = threadIdx.x;
    const int tx  = tid & 15;
    const int ty  = tid >> 4;

    unsigned long long acc[8][4];
#pragma unroll
    for (int i = 0; i < 8; i++)
#pragma unroll
        for (int j = 0; j < 4; j++) acc[i][j] = 0ull;

    const int lrow = tid >> 2;
    const int lcol = tid & 3;

    float4 ra[2], rb[2];
#pragma unroll
    for (int p = 0; p < 2; p++) {
        const int row = lrow + p * 64;
        ra[p] = *(const float4*)(Ap + (size_t)(bm + row) * KDIM + lcol * 4);
        rb[p] = *(const float4*)(B  + (size_t)(bn + row) * KDIM + lcol * 4);
    }

    for (int kt = 0; kt < KDIM; kt += 16) {
#pragma unroll
        for (int p = 0; p < 2; p++) {
            const int row = lrow + p * 64;
            As[lcol * 4 + 0][row] = ra[p].x; As[lcol * 4 + 1][row] = ra[p].y;
            As[lcol * 4 + 2][row] = ra[p].z; As[lcol * 4 + 3][row] = ra[p].w;
            Bs[lcol * 4 + 0][row] = rb[p].x; Bs[lcol * 4 + 1][row] = rb[p].y;
            Bs[lcol * 4 + 2][row] = rb[p].z; Bs[lcol * 4 + 3][row] = rb[p].w;
        }
        __syncthreads();

        if (kt + 16 < KDIM) {
#pragma unroll
            for (int p = 0; p < 2; p++) {
                const int row = lrow + p * 64;
                ra[p] = *(const float4*)(Ap + (size_t)(bm + row) * KDIM + kt + 16 + lcol * 4);
                rb[p] = *(const float4*)(B  + (size_t)(bn + row) * KDIM + kt + 16 + lcol * 4);
            }
        }

#pragma unroll
        for (int kk = 0; kk < 16; kk++) {
            float4 a0 = *(const float4*)&As[kk][ty * 8];
            float4 a1 = *(const float4*)&As[kk][ty * 8 + 4];
            ulonglong2 b0 = *(const ulonglong2*)&Bs[kk][tx * 4];
            ulonglong2 b1 = *(const ulonglong2*)&Bs[kk][64 + tx * 4];
            unsigned long long ad[8];
            ad[0] = dup2(a0.x); ad[1] = dup2(a0.y); ad[2] = dup2(a0.z); ad[3] = dup2(a0.w);
            ad[4] = dup2(a1.x); ad[5] = dup2(a1.y); ad[6] = dup2(a1.z); ad[7] = dup2(a1.w);
#pragma unroll
            for (int i = 0; i < 8; i++) {
                fma2(acc[i][0], ad[i], b0.x);
                fma2(acc[i][1], ad[i], b0.y);
                fma2(acc[i][2], ad[i], b1.x);
                fma2(acc[i][3], ad[i], b1.y);
            }
        }
        __syncthreads();
    }

    float4 bs0 = *(const float4*)&bias[bn + tx * 4];
    float4 bs1 = *(const float4*)&bias[bn + 64 + tx * 4];
#pragma unroll
    for (int i = 0; i < 8; i++) {
        const int m = bm + ty * 8 + i;
        float2 p01 = unpk(acc[i][0]);
        float2 p23 = unpk(acc[i][1]);
        float2 q01 = unpk(acc[i][2]);
        float2 q23 = unpk(acc[i][3]);
        float4 o0 = make_float4(p01.x + bs0.x, p01.y + bs0.y, p23.x + bs0.z, p23.y + bs0.w);
        float4 o1 = make_float4(q01.x + bs1.x, q01.y + bs1.y, q23.x + bs1.z, q23.y + bs1.w);
        if (MODE == 0 && m < BATCH) {
            const int n0 = bn + tx * 4;
            const int n1 = bn + 64 + tx * 4;
            o0.x += img[m * HDIM + ((n0 + 0) & (HDIM - 1))];
            o0.y += img[m * HDIM + ((n0 + 1) & (HDIM - 1))];
            o0.z += img[m * HDIM + ((n0 + 2) & (HDIM - 1))];
            o0.w += img[m * HDIM + ((n0 + 3) & (HDIM - 1))];
            o1.x += img[m * HDIM + ((n1 + 0) & (HDIM - 1))];
            o1.y += img[m * HDIM + ((n1 + 1) & (HDIM - 1))];
            o1.z += img[m * HDIM + ((n1 + 2) & (HDIM - 1))];
            o1.w += img[m * HDIM + ((n1 + 3) & (HDIM - 1))];
        }
        *(float4*)(Cp + (size_t)m * NDIM + bn + tx * 4)      = o0;
        *(float4*)(Cp + (size_t)m * NDIM + bn + 64 + tx * 4) = o1;
    }
}

/* ------------------------------------------------------------------ */
__device__ __forceinline__ void grid_barrier(int slot) {
    __syncthreads();
    if (threadIdx.x == 0) {
        __threadfence();
        unsigned ticket = atomicAdd(&g_bar[slot], 1u);
        unsigned target = (ticket / NBLK_LSTM + 1u) * NBLK_LSTM;
        while (*((volatile unsigned*)&g_bar[slot]) < target) { }
        __threadfence();
    }
    __syncthreads();
}

/* ------------------------------------------------------------------ */
/* Persistent LSTM recurrence — 2D register-blocked micro-tile.       */
/* 512 thr = 16 warps: (bg 0..3, rg 0..1, ks 0..1); lane = (bl, rl).  */
/* Thread tile: 4 batches x 2 gate-rows, f32x2 accs over k-pairs.     */
/* W smem: [32 r][1024], quad-swizzled k4 ^ rl  (conflict-free).      */
/* H smem: [64 b][132], quad-swizzled k4 ^ ((b>>2)&3) (conflict-free).*/
/* k split in halves across ks; partials summed via pre[2][32][68].   */
/* ------------------------------------------------------------------ */
#define HS_STRIDE 132
#define PRE_STRIDE 68
#define PRE_SLOT (32 * PRE_STRIDE)

__global__ __launch_bounds__(512, 1)
void lstm_kernel(const float* __restrict__ Whh,
                 const float* __restrict__ bhh) {
    extern __shared__ __align__(16) float smem[];
    float* Ws  = smem;                           /* 32*1024 = 128 KB  */
    float* hsm = smem + 32 * 1024;               /* 64*132  = 33 KB   */
    float* pre = hsm + 64 * HS_STRIDE;           /* 2*32*68 = 17 KB   */

    const int tid = threadIdx.x;
    const int j0  = blockIdx.x * 8;

    const int w  = tid >> 5, l = tid & 31;
    const int bg = w & 3;
    const int rg = (w >> 2) & 1;
    const int ks = w >> 3;
    const int bl = l & 3;
    const int rl = l >> 2;
    const int bQ = bg * 16 + bl * 4;      /* batch quad base */
    const int rP = rg * 16 + rl * 2;      /* gate-row pair base */

    /* gate identity: one (b, unit) cell per thread */
    const int gu = tid & 7;
    const int gb = tid >> 3;

    /* staging identity */
    const int sb  = tid >> 3;             /* 0..63 */
    const int sk4 = tid & 7;
    const int ssw = (sb >> 2) & 3;

    /* stage Whh, quad-swizzled (once) */
    for (int idx = tid; idx < 32 * 256; idx += 512) {
        const int r  = idx & 31;
        const int k4 = idx >> 5;
        const int uu = r >> 2, gg = r & 3;
        float4 wv = *(const float4*)&Whh[(size_t)(gg * HDIM + j0 + uu) * HDIM + k4 * 4];
        const int q = k4 ^ ((r >> 1) & 7);
        /* STS.64 pairs keep any r aligned */
        *(float2*)&Ws[r * 1024 + q * 4]     = make_float2(wv.x, wv.y);
        *(float2*)&Ws[r * 1024 + q * 4 + 2] = make_float2(wv.z, wv.w);
    }
    const int r0 = rP, r1 = rP + 1;
    const float bias0 = bhh[(r0 & 3) * HDIM + j0 + (r0 >> 2)];
    const float bias1 = bhh[(r1 & 3) * HDIM + j0 + (r1 >> 2)];
    float c = 0.0f;
    __syncthreads();

    const float* wp0 = Ws + r0 * 1024;
    const float* wp1 = Ws + r1 * 1024;

    for (int t = 0; t < T_LEN; t++) {
        /* xproj prefetch (ks==0 warps add it later) */
        float xp[4][2];
        if (ks == 0) {
            const float* xb = g_xproj + (size_t)t * BATCH * G4 + j0;
            const int off0 = (r0 & 3) * HDIM + (r0 >> 2);
            const int off1 = (r1 & 3) * HDIM + (r1 >> 2);
#pragma unroll
            for (int j = 0; j < 4; j++) {
                xp[j][0] = __ldg(xb + (size_t)(bQ + j) * G4 + off0);
                xp[j][1] = __ldg(xb + (size_t)(bQ + j) * G4 + off1);
            }
        }

        unsigned long long acc[4][2];
#pragma unroll
        for (int j = 0; j < 4; j++) { acc[j][0] = 0ull; acc[j][1] = 0ull; }

        if (t > 0) {
            const float* __restrict__ hp = g_hs + (size_t)(t - 1) * BATCH * HDIM;
            float4 st[4];
#pragma unroll
            for (int i = 0; i < 4; i++)
                st[i] = *(const float4*)&hp[(size_t)sb * HDIM + (sk4 + 8 * i) * 4];

#pragma unroll 1
            for (int ch = 0; ch < 8; ch++) {
                __syncthreads();   /* hs buffer free */
#pragma unroll
                for (int i = 0; i < 4; i++) {
                    const int k4l = sk4 + 8 * i;             /* 0..31 */
                    *(float4*)&hsm[sb * HS_STRIDE + ((k4l ^ ssw) << 2)] = st[i];
                }
                if (ch < 7) {
#pragma unroll
                    for (int i = 0; i < 4; i++)
                        st[i] = *(const float4*)&hp[(size_t)sb * HDIM +
                                                    (ch + 1) * 128 + (sk4 + 8 * i) * 4];
                }
                __syncthreads();   /* hs ready */

                const int mbase = ks * 16;
#pragma unroll 4
                for (int mm = 0; mm < 16; mm++) {
                    const int m  = mbase + mm;        /* quad in chunk 0..31 */
                    const int Mg = ch * 32 + m;       /* global k4 */
                    const int woff = ((Mg ^ rl) << 2);
                    ulonglong2 W0 = *(const ulonglong2*)(wp0 + woff);
                    ulonglong2 W1 = *(const ulonglong2*)(wp1 + woff);
                    const int hoff = ((m ^ bl) << 2);
#pragma unroll
                    for (int j = 0; j < 4; j++) {
                        ulonglong2 H = *(const ulonglong2*)
                            (hsm + (bQ + j) * HS_STRIDE + hoff);
                        fma2(acc[j][0], H.x, W0.x);
                        fma2(acc[j][0], H.y, W0.y);
                        fma2(acc[j][1], H.x, W1.x);
                        fma2(acc[j][1], H.y, W1.y);
                    }
                }
            }
        }

        /* fold partials (+ xproj/bias on ks==0) -> pre[ks][r][b] */
        {
            float4 v0, v1;
            float2 a;
            a = unpk(acc[0][0]); v0.x = a.x + a.y;
            a = unpk(acc[1][0]); v0.y = a.x + a.y;
            a = unpk(acc[2][0]); v0.z = a.x + a.y;
            a = unpk(acc[3][0]); v0.w = a.x + a.y;
            a = unpk(acc[0][1]); v1.x = a.x + a.y;
            a = unpk(acc[1][1]); v1.y = a.x + a.y;
            a = unpk(acc[2][1]); v1.z = a.x + a.y;
            a = unpk(acc[3][1]); v1.w = a.x + a.y;
            if (ks == 0) {
                v0.x += xp[0][0] + bias0; v0.y += xp[1][0] + bias0;
                v0.z += xp[2][0] + bias0; v0.w += xp[3][0] + bias0;
                v1.x += xp[0][1] + bias1; v1.y += xp[1][1] + bias1;
                v1.z += xp[2][1] + bias1; v1.w += xp[3][1] + bias1;
            }
            *(float4*)&pre[ks * PRE_SLOT + r0 * PRE_STRIDE + bQ] = v0;
            *(float4*)&pre[ks * PRE_SLOT + r1 * PRE_STRIDE + bQ] = v1;
        }
        __syncthreads();

        /* gate math: one (batch, unit) cell per thread */
        {
            float s[4];
#pragma unroll
            for (int g2 = 0; g2 < 4; g2++) {
                const int rr = gu * 4 + g2;
                s[g2] = pre[rr * PRE_STRIDE + gb] +
                        pre[PRE_SLOT + rr * PRE_STRIDE + gb];
            }
            float ig = sigmoidf_(s[0]);
            float fg = sigmoidf_(s[1]);
            float gg = tanhf(s[2]);
            float og = sigmoidf_(s[3]);
            c = fg * c + ig * gg;
            g_hs[(size_t)t * BATCH * HDIM + (size_t)gb * HDIM + j0 + gu] =
                og * tanhf(c);
        }

        if (t < T_LEN - 1) grid_barrier(t);
    }
}

/* ------------------------------------------------------------------ */
__global__ __launch_bounds__(256)
void logsoftmax_kernel(float* __restrict__ out) {
    __shared__ float red[8];
    const int row = blockIdx.x;
    const int tid = threadIdx.x;
    const float* x = g_logits + (size_t)row * INDIM;
    float v0 = x[tid];
    float v1 = x[tid + 256];

    float m = fmaxf(v0, v1);
#pragma unroll
    for (int o = 16; o; o >>= 1) m = fmaxf(m, __shfl_xor_sync(0xffffffffu, m, o));
    if ((tid & 31) == 0) red[tid >> 5] = m;
    __syncthreads();
    float M = fmaxf(fmaxf(fmaxf(red[0], red[1]), fmaxf(red[2], red[3])),
                    fmaxf(fmaxf(red[4], red[5]), fmaxf(red[6], red[7])));
    __syncthreads();

    float s = expf(v0 - M) + expf(v1 - M);
#pragma unroll
    for (int o = 16; o; o >>= 1) s += __shfl_xor_sync(0xffffffffu, s, o);
    if ((tid & 31) == 0) red[tid >> 5] = s;
    __syncthreads();
    float S = (red[0] + red[1]) + (red[2] + red[3]) +
              (red[4] + red[5]) + (red[6] + red[7]);
    float lse = M + logf(S);

    out[(size_t)row * INDIM + tid]       = v0 - lse;
    out[(size_t)row * INDIM + tid + 256] = v1 - lse;
}

/* ------------------------------------------------------------------ */
extern "C" void kernel_launch(void* const* d_in, const int* in_sizes, int n_in,
                              void* d_out, int out_size) {
    const float* inp  = (const float*)d_in[0];
    const float* img  = (const float*)d_in[1];
    const float* Wxh  = (const float*)d_in[2];
    const float* bxh  = (const float*)d_in[3];
    const float* Whh  = (const float*)d_in[4];
    const float* bhh  = (const float*)d_in[5];
    const float* Wout = (const float*)d_in[6];
    const float* bout = (const float*)d_in[7];
    float* out = (float*)d_out;

    const int lstm_smem =
        (32 * 1024 + 64 * HS_STRIDE + 2 * PRE_SLOT) * (int)sizeof(float); /* ~178 KB */
    cudaFuncSetAttribute(lstm_kernel,
                         cudaFuncAttributeMaxDynamicSharedMemorySize, lstm_smem);

    gemm_nt<INDIM, G4, 0><<<dim3(G4 / 128, M_TOT / 128), 256>>>(inp, Wxh, bxh, img);
    lstm_kernel<<<NBLK_LSTM, 512, lstm_smem>>>(Whh, bhh);
    gemm_nt<HDIM, INDIM, 1><<<dim3(INDIM / 128, M_TOT / 128), 256>>>(nullptr, Wout, bout, nullptr);
    logsoftmax_kernel<<<M_TOT, 256>>>(out);
}

// round 7
// speedup vs baseline: 8.1046x; 1.8577x over previous
#include <cuda_runtime.h>
#include <math.h>

#define T_LEN 256
#define BATCH 64
#define INDIM 512
#define HDIM  1024
#define M_TOT (T_LEN * BATCH)   /* 16384 */
#define G4    (4 * HDIM)        /* 4096  */
#define NBLK_LSTM 128

/* ------------------------------------------------------------------ */
__device__ float    g_xproj [M_TOT * G4];
__device__ float    g_hs    [M_TOT * HDIM];
__device__ float    g_logits[M_TOT * INDIM];
__device__ unsigned g_bar   [T_LEN];

/* ------------------------------------------------------------------ */
__device__ __forceinline__ float sigmoidf_(float x) {
    return 1.0f / (1.0f + expf(-x));
}
__device__ __forceinline__ void cp_async16(float* smem_dst, const float* gsrc) {
    unsigned sa = (unsigned)__cvta_generic_to_shared(smem_dst);
    asm volatile("cp.async.cg.shared.global [%0], [%1], 16;\n" :: "r"(sa), "l"(gsrc));
}
__device__ __forceinline__ void cp_commit() {
    asm volatile("cp.async.commit_group;\n" ::: "memory");
}
__device__ __forceinline__ void cp_wait0() {
    asm volatile("cp.async.wait_group 0;\n" ::: "memory");
}
__device__ __forceinline__ void cp_wait1() {
    asm volatile("cp.async.wait_group 1;\n" ::: "memory");
}

/* tf32 mma m16n8k8: D = A(row) * B(col) + D, fp32 accum.
   a: thread holds A[r=lane/4 (+8)][c=lane%4 (+4)]
   b: thread holds B[k=lane%4 (+4)][n=lane/4]
   c: thread holds C[r=lane/4 (+8)][c=2*(lane%4)+{0,1}]                 */
__device__ __forceinline__ void mma_tf32(float* c, const unsigned* a,
                                         const unsigned* b) {
    asm volatile(
        "mma.sync.aligned.m16n8k8.row.col.f32.tf32.tf32.f32 "
        "{%0,%1,%2,%3}, {%4,%5,%6,%7}, {%8,%9}, {%0,%1,%2,%3};"
        : "+f"(c[0]), "+f"(c[1]), "+f"(c[2]), "+f"(c[3])
        : "r"(a[0]), "r"(a[1]), "r"(a[2]), "r"(a[3]), "r"(b[0]), "r"(b[1]));
}
__device__ __forceinline__ unsigned fbits(float x) { return __float_as_uint(x); }

/* ------------------------------------------------------------------ */
/* tf32 GEMM:  C[m][n] = A[m][k] * B[n][k]^T + bias  (NT)             */
/* CTA 128x128, 8 warps (2 m x 4 n), warp tile 64x32.                 */
/* smem stride 36 (=4 mod 32): all fragment LDS conflict-free.        */
/* ------------------------------------------------------------------ */
#define GST 36

template <int KDIM, int NDIM, int MODE>
__global__ __launch_bounds__(256, 2)
void gemm_tf32(const float* __restrict__ Aext,
               const float* __restrict__ B,
               const float* __restrict__ bias,
               const float* __restrict__ img) {
    extern __shared__ __align__(16) float sm[];
    /* [buf][A/B][128][GST] */
    const float* __restrict__ Ap = (MODE == 0) ? Aext : g_hs;
    float* __restrict__       Cp = (MODE == 0) ? g_xproj : g_logits;

    const int bm   = blockIdx.y * 128;
    const int bn   = blockIdx.x * 128;
    const int tid  = threadIdx.x;
    const int lane = tid & 31;
    const int warp = tid >> 5;
    const int wm   = warp & 1;          /* m-slice of 64  */
    const int wn   = warp >> 1;         /* n-slice of 32  */

    float acc[4][4][4];
#pragma unroll
    for (int i = 0; i < 4; i++)
#pragma unroll
        for (int j = 0; j < 4; j++)
#pragma unroll
            for (int v = 0; v < 4; v++) acc[i][j][v] = 0.0f;

    const int NCH = KDIM / 32;

    /* stage chunk 0 */
    {
        float* As = sm;
        float* Bs = sm + 128 * GST;
#pragma unroll
        for (int i = 0; i < 4; i++) {
            const int idx = tid + i * 256;       /* 0..1023 */
            const int row = idx >> 3, q = idx & 7;
            cp_async16(&As[row * GST + q * 4], Ap + (size_t)(bm + row) * KDIM + q * 4);
            cp_async16(&Bs[row * GST + q * 4], B  + (size_t)(bn + row) * KDIM + q * 4);
        }
        cp_commit();
    }

    for (int ck = 0; ck < NCH; ck++) {
        const int buf = ck & 1;
        if (ck + 1 < NCH) {
            float* As = sm + ((ck + 1) & 1) * (256 * GST);
            float* Bs = As + 128 * GST;
            const int kt = (ck + 1) * 32;
#pragma unroll
            for (int i = 0; i < 4; i++) {
                const int idx = tid + i * 256;
                const int row = idx >> 3, q = idx & 7;
                cp_async16(&As[row * GST + q * 4],
                           Ap + (size_t)(bm + row) * KDIM + kt + q * 4);
                cp_async16(&Bs[row * GST + q * 4],
                           B + (size_t)(bn + row) * KDIM + kt + q * 4);
            }
            cp_commit();
            cp_wait1();
        } else {
            cp_wait0();
        }
        __syncthreads();

        const float* As = sm + buf * (256 * GST) + (wm * 64) * GST;
        const float* Bs = sm + buf * (256 * GST) + 128 * GST + (wn * 32) * GST;
#pragma unroll
        for (int ks = 0; ks < 4; ks++) {
            const int col = ks * 8 + (lane & 3);
            unsigned af[4][4];
#pragma unroll
            for (int mt = 0; mt < 4; mt++) {
                const int row = mt * 16 + (lane >> 2);
                af[mt][0] = fbits(As[row * GST + col]);
                af[mt][1] = fbits(As[(row + 8) * GST + col]);
                af[mt][2] = fbits(As[row * GST + col + 4]);
                af[mt][3] = fbits(As[(row + 8) * GST + col + 4]);
            }
#pragma unroll
            for (int nt = 0; nt < 4; nt++) {
                const int nr = nt * 8 + (lane >> 2);
                unsigned bf[2];
                bf[0] = fbits(Bs[nr * GST + col]);
                bf[1] = fbits(Bs[nr * GST + col + 4]);
#pragma unroll
                for (int mt = 0; mt < 4; mt++)
                    mma_tf32(acc[mt][nt], af[mt], bf);
            }
        }
        __syncthreads();
    }

    /* epilogue */
#pragma unroll
    for (int mt = 0; mt < 4; mt++) {
#pragma unroll
        for (int nt = 0; nt < 4; nt++) {
            const int m = bm + wm * 64 + mt * 16 + (lane >> 2);
            const int n = bn + wn * 32 + nt * 8 + 2 * (lane & 3);
            const float2 bv = *(const float2*)&bias[n];
            float o0 = acc[mt][nt][0] + bv.x;
            float o1 = acc[mt][nt][1] + bv.y;
            float o2 = acc[mt][nt][2] + bv.x;
            float o3 = acc[mt][nt][3] + bv.y;
            if (MODE == 0) {
                if (m < BATCH) {
                    o0 += img[m * HDIM + (n & (HDIM - 1))];
                    o1 += img[m * HDIM + ((n + 1) & (HDIM - 1))];
                }
                if (m + 8 < BATCH) {
                    o2 += img[(m + 8) * HDIM + (n & (HDIM - 1))];
                    o3 += img[(m + 8) * HDIM + ((n + 1) & (HDIM - 1))];
                }
            }
            *(float2*)(Cp + (size_t)m * NDIM + n)       = make_float2(o0, o1);
            *(float2*)(Cp + (size_t)(m + 8) * NDIM + n) = make_float2(o2, o3);
        }
    }
}

/* ------------------------------------------------------------------ */
__device__ __forceinline__ void grid_barrier(int slot) {
    __syncthreads();
    if (threadIdx.x == 0) {
        __threadfence();
        unsigned ticket = atomicAdd(&g_bar[slot], 1u);
        unsigned target = (ticket / NBLK_LSTM + 1u) * NBLK_LSTM;
        while (*((volatile unsigned*)&g_bar[slot]) < target) { }
        __threadfence();
    }
    __syncthreads();
}

/* ------------------------------------------------------------------ */
/* Persistent LSTM recurrence — tf32 tensor-core dot engine.          */
/* 128 CTAs x 256 thr (8 warps = 4 m-slices x 2 k-groups).            */
/* CTA owns 32 gate rows r=u*4+g (8 units). W resident in smem,       */
/* stride 1028; h double-buffered cp.async chunks of 128, stride 132; */
/* per-kg partials folded via pre[2][64][36].                         */
/* ------------------------------------------------------------------ */
#define WST 1028
#define HST 132
#define PST 36
#define HS_OFF  (32 * WST)                 /* floats */
#define PRE_OFF (HS_OFF + 2 * 64 * HST)
#define PRE_SZ  (64 * PST)

__global__ __launch_bounds__(256, 1)
void lstm_kernel(const float* __restrict__ Whh,
                 const float* __restrict__ bhh) {
    extern __shared__ __align__(16) float sm[];
    float* Ws  = sm;
    float* hs0 = sm + HS_OFF;
    float* pre = sm + PRE_OFF;

    const int tid  = threadIdx.x;
    const int lane = tid & 31;
    const int warp = tid >> 5;
    const int mg   = warp & 3;     /* m-slice (16 batches) */
    const int kg   = warp >> 2;    /* k-group 0/1          */
    const int j0   = blockIdx.x * 8;

    /* gate identity: cells (gb, gu0) and (gb, gu1) */
    const int gb  = tid >> 2;
    const int gu0 = tid & 3;
    const int gu1 = gu0 + 4;

    /* h staging identity */
    const int sb = tid & 63;
    const int sq = tid >> 6;      /* 0..3 */

    /* stage Whh (once): Ws[r][k], r = u*4+g */
    for (int idx = tid; idx < 32 * 256; idx += 256) {
        const int r = idx & 31, k4 = idx >> 5;
        const int u = r >> 2, g = r & 3;
        float4 w = *(const float4*)&Whh[(size_t)(g * HDIM + j0 + u) * HDIM + k4 * 4];
        *(float4*)&Ws[r * WST + k4 * 4] = w;
    }
    float bh0[4], bh1[4];
#pragma unroll
    for (int g = 0; g < 4; g++) {
        bh0[g] = bhh[g * HDIM + j0 + gu0];
        bh1[g] = bhh[g * HDIM + j0 + gu1];
    }
    float c0 = 0.0f, c1 = 0.0f;
    __syncthreads();

    for (int t = 0; t < T_LEN; t++) {
        /* prefetch xproj for this thread's 2 cells (overlaps all compute) */
        float xp0[4], xp1[4];
        {
            const float* xb = g_xproj + (size_t)t * BATCH * G4 + (size_t)gb * G4 + j0;
#pragma unroll
            for (int g = 0; g < 4; g++) {
                xp0[g] = __ldg(xb + g * HDIM + gu0);
                xp1[g] = __ldg(xb + g * HDIM + gu1);
            }
        }

        if (t > 0) {
            const float* __restrict__ hp = g_hs + (size_t)(t - 1) * BATCH * HDIM;

            /* stage chunk 0 */
#pragma unroll
            for (int i = 0; i < 8; i++) {
                const int k4 = sq + 4 * i;
                cp_async16(&hs0[sb * HST + k4 * 4], hp + (size_t)sb * HDIM + k4 * 4);
            }
            cp_commit();

            float acc[4][4];
#pragma unroll
            for (int nt = 0; nt < 4; nt++)
#pragma unroll
                for (int v = 0; v < 4; v++) acc[nt][v] = 0.0f;

#pragma unroll 1
            for (int ch = 0; ch < 8; ch++) {
                if (ch < 7) {
                    float* dst = hs0 + ((ch + 1) & 1) * (64 * HST);
#pragma unroll
                    for (int i = 0; i < 8; i++) {
                        const int k4 = sq + 4 * i;
                        cp_async16(&dst[sb * HST + k4 * 4],
                                   hp + (size_t)sb * HDIM + (ch + 1) * 128 + k4 * 4);
                    }
                    cp_commit();
                    cp_wait1();
                } else {
                    cp_wait0();
                }
                __syncthreads();

                const float* Ab = hs0 + (ch & 1) * (64 * HST) + (mg * 16) * HST
                                  + kg * 64;
                const float* Wb = Ws + ch * 128 + kg * 64;
#pragma unroll
                for (int ks = 0; ks < 8; ks++) {
                    const int col = ks * 8 + (lane & 3);
                    unsigned af[4];
                    {
                        const float* a = Ab + (lane >> 2) * HST + col;
                        af[0] = fbits(a[0]);
                        af[1] = fbits(a[8 * HST]);
                        af[2] = fbits(a[4]);
                        af[3] = fbits(a[8 * HST + 4]);
                    }
#pragma unroll
                    for (int nt = 0; nt < 4; nt++) {
                        const float* b = Wb + (nt * 8 + (lane >> 2)) * WST + col;
                        unsigned bf[2];
                        bf[0] = fbits(b[0]);
                        bf[1] = fbits(b[4]);
                        mma_tf32(acc[nt], af, bf);
                    }
                }
                __syncthreads();
            }

            /* write per-kg partials: pre[kg][m][n] */
            {
                float* pg = pre + kg * PRE_SZ;
#pragma unroll
                for (int nt = 0; nt < 4; nt++) {
                    const int m = mg * 16 + (lane >> 2);
                    const int n = nt * 8 + 2 * (lane & 3);
                    *(float2*)&pg[m * PST + n]       = make_float2(acc[nt][0], acc[nt][1]);
                    *(float2*)&pg[(m + 8) * PST + n] = make_float2(acc[nt][2], acc[nt][3]);
                }
            }
        }
        __syncthreads();

        /* gate math: 2 cells per thread */
        {
            float s0[4], s1[4];
            if (t > 0) {
                float4 p00 = *(const float4*)&pre[gb * PST + gu0 * 4];
                float4 p01 = *(const float4*)&pre[PRE_SZ + gb * PST + gu0 * 4];
                float4 p10 = *(const float4*)&pre[gb * PST + gu1 * 4];
                float4 p11 = *(const float4*)&pre[PRE_SZ + gb * PST + gu1 * 4];
                s0[0] = p00.x + p01.x; s0[1] = p00.y + p01.y;
                s0[2] = p00.z + p01.z; s0[3] = p00.w + p01.w;
                s1[0] = p10.x + p11.x; s1[1] = p10.y + p11.y;
                s1[2] = p10.z + p11.z; s1[3] = p10.w + p11.w;
            } else {
#pragma unroll
                for (int g = 0; g < 4; g++) { s0[g] = 0.0f; s1[g] = 0.0f; }
            }
#pragma unroll
            for (int g = 0; g < 4; g++) {
                s0[g] += xp0[g] + bh0[g];
                s1[g] += xp1[g] + bh1[g];
            }
            {
                float ig = sigmoidf_(s0[0]), fg = sigmoidf_(s0[1]);
                float gg = tanhf(s0[2]),     og = sigmoidf_(s0[3]);
                c0 = fg * c0 + ig * gg;
                g_hs[(size_t)t * BATCH * HDIM + (size_t)gb * HDIM + j0 + gu0] =
                    og * tanhf(c0);
            }
            {
                float ig = sigmoidf_(s1[0]), fg = sigmoidf_(s1[1]);
                float gg = tanhf(s1[2]),     og = sigmoidf_(s1[3]);
                c1 = fg * c1 + ig * gg;
                g_hs[(size_t)t * BATCH * HDIM + (size_t)gb * HDIM + j0 + gu1] =
                    og * tanhf(c1);
            }
        }

        if (t < T_LEN - 1) grid_barrier(t);
    }
}

/* ------------------------------------------------------------------ */
__global__ __launch_bounds__(256)
void logsoftmax_kernel(float* __restrict__ out) {
    __shared__ float red[8];
    const int row = blockIdx.x;
    const int tid = threadIdx.x;
    const float* x = g_logits + (size_t)row * INDIM;
    float v0 = x[tid];
    float v1 = x[tid + 256];

    float m = fmaxf(v0, v1);
#pragma unroll
    for (int o = 16; o; o >>= 1) m = fmaxf(m, __shfl_xor_sync(0xffffffffu, m, o));
    if ((tid & 31) == 0) red[tid >> 5] = m;
    __syncthreads();
    float M = fmaxf(fmaxf(fmaxf(red[0], red[1]), fmaxf(red[2], red[3])),
                    fmaxf(fmaxf(red[4], red[5]), fmaxf(red[6], red[7])));
    __syncthreads();

    float s = expf(v0 - M) + expf(v1 - M);
#pragma unroll
    for (int o = 16; o; o >>= 1) s += __shfl_xor_sync(0xffffffffu, s, o);
    if ((tid & 31) == 0) red[tid >> 5] = s;
    __syncthreads();
    float S = (red[0] + red[1]) + (red[2] + red[3]) +
              (red[4] + red[5]) + (red[6] + red[7]);
    float lse = M + logf(S);

    out[(size_t)row * INDIM + tid]       = v0 - lse;
    out[(size_t)row * INDIM + tid + 256] = v1 - lse;
}

/* ------------------------------------------------------------------ */
extern "C" void kernel_launch(void* const* d_in, const int* in_sizes, int n_in,
                              void* d_out, int out_size) {
    const float* inp  = (const float*)d_in[0];
    const float* img  = (const float*)d_in[1];
    const float* Wxh  = (const float*)d_in[2];
    const float* bxh  = (const float*)d_in[3];
    const float* Whh  = (const float*)d_in[4];
    const float* bhh  = (const float*)d_in[5];
    const float* Wout = (const float*)d_in[6];
    const float* bout = (const float*)d_in[7];
    float* out = (float*)d_out;

    const int gemm_smem = 2 * 2 * 128 * GST * (int)sizeof(float);      /* 73.7 KB  */
    const int lstm_smem = (PRE_OFF + 2 * PRE_SZ) * (int)sizeof(float); /* 217.6 KB */

    cudaFuncSetAttribute(gemm_tf32<INDIM, G4, 0>,
                         cudaFuncAttributeMaxDynamicSharedMemorySize, gemm_smem);
    cudaFuncSetAttribute(gemm_tf32<HDIM, INDIM, 1>,
                         cudaFuncAttributeMaxDynamicSharedMemorySize, gemm_smem);
    cudaFuncSetAttribute(lstm_kernel,
                         cudaFuncAttributeMaxDynamicSharedMemorySize, lstm_smem);

    gemm_tf32<INDIM, G4, 0><<<dim3(G4 / 128, M_TOT / 128), 256, gemm_smem>>>
        (inp, Wxh, bxh, img);
    lstm_kernel<<<NBLK_LSTM, 256, lstm_smem>>>(Whh, bhh);
    gemm_tf32<HDIM, INDIM, 1><<<dim3(INDIM / 128, M_TOT / 128), 256, gemm_smem>>>
        (nullptr, Wout, bout, nullptr);
    logsoftmax_kernel<<<M_TOT, 256>>>(out);
}